// round 1
// baseline (speedup 1.0000x reference)
#include <cuda_runtime.h>
#include <cstdint>

#define PI_F 3.14159265358979323846f
// Two scratch volumes: 2 batches x 256^3 complex64 = 256 MiB each.
static __device__ float2 g_A[33554432];
static __device__ float2 g_B[33554432];

__device__ __forceinline__ float2 cmul(float2 a, float2 b){
    return make_float2(a.x*b.x - a.y*b.y, a.x*b.y + a.y*b.x);
}
__device__ __forceinline__ int brev8(int i){ return (int)(__brev((unsigned)i) >> 24); }

// 256-pt radix-2 DIT FFT, data bit-reversed in shared, 128 threads = 1 line.
template<int SIGN>
__device__ __forceinline__ void fft256_128t(float2* s, int tid){
#pragma unroll
    for (int st = 0; st < 8; ++st){
        int half = 1 << st;
        int pos = tid & (half - 1);
        int i0 = ((tid >> st) << (st + 1)) + pos;
        float ang = (float)SIGN * PI_F * (float)pos / (float)half;
        float sn, cs; __sincosf(ang, &sn, &cs);
        __syncthreads();
        float2 a = s[i0];
        float2 b = cmul(make_float2(cs, sn), s[i0 + half]);
        s[i0]        = make_float2(a.x + b.x, a.y + b.y);
        s[i0 + half] = make_float2(a.x - b.x, a.y - b.y);
    }
    __syncthreads();
}

// Same FFT but 16 threads per line (u in [0,16)), 8 butterflies each per stage.
template<int SIGN>
__device__ __forceinline__ void fft256_16t(float2* s, int u){
#pragma unroll
    for (int st = 0; st < 8; ++st){
        int half = 1 << st;
        __syncthreads();
#pragma unroll
        for (int k = 0; k < 8; ++k){
            int j = u + (k << 4);
            int pos = j & (half - 1);
            int i0 = ((j >> st) << (st + 1)) + pos;
            float ang = (float)SIGN * PI_F * (float)pos / (float)half;
            float sn, cs; __sincosf(ang, &sn, &cs);
            float2 a = s[i0];
            float2 b = cmul(make_float2(cs, sn), s[i0 + half]);
            s[i0]        = make_float2(a.x + b.x, a.y + b.y);
            s[i0 + half] = make_float2(a.x - b.x, a.y - b.y);
        }
    }
    __syncthreads();
}

// Forward X-pass fused with prep: v = sqrt(relu(in * (z/127)^2)), zero-pad to 256.
// Lines: (b, z<128, y<128). Writes full 256 outputs to g_A.
__global__ void k_fwd_x(const float* __restrict__ in){
    __shared__ float2 s[256];
    int y = blockIdx.x, zz = blockIdx.y, b = blockIdx.z;
    int tid = threadIdx.x;
    float g = (float)zz * (1.0f/127.0f);
    float g2 = g*g;
    const float* row = in + (((size_t)b*128 + zz)*128 + y)*128;
#pragma unroll
    for (int h = 0; h < 2; ++h){
        int i = tid + (h << 7);
        int src = brev8(i);
        float v = 0.0f;
        if (src < 128) v = sqrtf(fmaxf(row[src]*g2, 0.0f));
        s[i] = make_float2(v, 0.0f);
    }
    fft256_128t<-1>(s, tid);
    float2* outl = g_A + (((size_t)b*256 + zz)*256 + y)*256;
    outl[tid]       = s[tid];
    outl[tid + 128] = s[tid + 128];
}

// Forward Y-pass: lines (b, z<128, all x), read y<128 (zero-pad), write all y.
__global__ void k_fwd_y(){
    __shared__ float2 s[16*257];
    int x0 = blockIdx.x << 4, zz = blockIdx.y, b = blockIdx.z;
    int tid = threadIdx.x, xl = tid & 15, u = tid >> 4;
    float2* base = g_A + ((size_t)b << 24) + ((size_t)zz << 16) + x0;
    float2* sl = s + xl*257;
#pragma unroll
    for (int c = 0; c < 8; ++c){
        int yy = (c << 4) + u;
        sl[brev8(yy)]       = base[(size_t)yy*256 + xl];
        sl[brev8(yy + 128)] = make_float2(0.f, 0.f);
    }
    fft256_16t<-1>(sl, u);
#pragma unroll
    for (int c = 0; c < 16; ++c){
        int yy = (c << 4) + u;
        base[(size_t)yy*256 + xl] = sl[yy];
    }
}

// Forward Z-pass: lines (b, all y, all x), read z<128 (zero-pad), write all z.
__global__ void k_fwd_z(){
    __shared__ float2 s[16*257];
    int x0 = blockIdx.x << 4, y = blockIdx.y, b = blockIdx.z;
    int tid = threadIdx.x, xl = tid & 15, u = tid >> 4;
    float2* base = g_A + ((size_t)b << 24) + ((size_t)y << 8) + x0;
    float2* sl = s + xl*257;
#pragma unroll
    for (int c = 0; c < 8; ++c){
        int zz = (c << 4) + u;
        sl[brev8(zz)]       = base[(size_t)zz*65536 + xl];
        sl[brev8(zz + 128)] = make_float2(0.f, 0.f);
    }
    fft256_16t<-1>(sl, u);
#pragma unroll
    for (int c = 0; c < 16; ++c){
        int zz = (c << 4) + u;
        base[(size_t)zz*65536 + xl] = sl[zz];
    }
}

// Stolt resample. Output already in *unshifted* coords (both fftshifts folded
// into XOR-128 index maps). Only jz in [1,127] can be nonzero (z mask).
// px = sx-0.5, py = sy-0.5 exactly -> 0.25-weighted 2x2 stencil in x,y;
// true interpolation only along z.
__global__ void k_resample(){
    int jx = threadIdx.x;           // 0..255
    int jy = blockIdx.x;            // 0..255
    int jz = blockIdx.y + 1;        // 1..127
    int b  = blockIdx.z;
    int sx = jx ^ 128, sy = jy ^ 128, sz = jz + 128;   // shifted coords
    float gz = (float)(sz - 128) * (1.0f/128.0f);
    float gy = (float)(sy - 128) * (1.0f/128.0f);
    float gx = (float)(sx - 128) * (1.0f/128.0f);
    const float trange = 128.0f * 0.01f;
    const float tq = (128.0f * trange) / (128.0f * 1.0f * 4.0f);
    const float fk = tq * tq;
    float gznew = sqrtf(fk*(gx*gx + gy*gy) + gz*gz);
    float pz = ((gznew + 1.0f)*256.0f - 1.0f)*0.5f;
    float z0f = floorf(pz);
    float dz = pz - z0f;
    int z0 = (int)z0f;
    float accx = 0.f, accy = 0.f;
    const float2* Ab = g_A + ((size_t)b << 24);
#pragma unroll
    for (int tz = 0; tz < 2; ++tz){
        int iz = z0 + tz;
        if (iz < 0 || iz > 255) continue;
        float wz = tz ? dz : (1.0f - dz);
        size_t zoff = (size_t)(iz ^ 128) << 16;
#pragma unroll
        for (int ty = 0; ty < 2; ++ty){
            int iy = sy - 1 + ty;               // <= 255 always
            if (iy < 0) continue;
            size_t yoff = (size_t)(iy ^ 128) << 8;
#pragma unroll
            for (int tx = 0; tx < 2; ++tx){
                int ix = sx - 1 + tx;
                if (ix < 0) continue;
                float2 v = __ldg(&Ab[zoff + yoff + (size_t)(ix ^ 128)]);
                accx += wz * v.x;
                accy += wz * v.y;
            }
        }
    }
    float fac = 0.25f * gz / (gznew + 1e-8f);   // gz > 0 for sz >= 129
    size_t o = ((size_t)b << 24) + ((size_t)jz << 16) + ((size_t)jy << 8) + (size_t)jx;
    g_B[o] = make_float2(accx * fac, accy * fac);
}

// Inverse X-pass: lines (b, z in [1,128), all y). Read 256, write x<128 (scaled 1/256).
__global__ void k_inv_x(){
    __shared__ float2 s[256];
    int y = blockIdx.x, zz = blockIdx.y + 1, b = blockIdx.z;
    int tid = threadIdx.x;
    float2* line = g_B + ((size_t)b << 24) + ((size_t)zz << 16) + ((size_t)y << 8);
    s[tid]       = line[brev8(tid)];
    s[tid + 128] = line[brev8(tid + 128)];
    fft256_128t<1>(s, tid);
    float2 v = s[tid];
    line[tid] = make_float2(v.x * (1.f/256.f), v.y * (1.f/256.f));
}

// Inverse Y-pass: lines (b, z in [1,128), x<128). Read all y, write y<128 (scaled).
__global__ void k_inv_y(){
    __shared__ float2 s[16*257];
    int x0 = blockIdx.x << 4, zz = blockIdx.y + 1, b = blockIdx.z;
    int tid = threadIdx.x, xl = tid & 15, u = tid >> 4;
    float2* base = g_B + ((size_t)b << 24) + ((size_t)zz << 16) + x0;
    float2* sl = s + xl*257;
#pragma unroll
    for (int c = 0; c < 16; ++c){
        int yy = (c << 4) + u;
        sl[brev8(yy)] = base[(size_t)yy*256 + xl];
    }
    fft256_16t<1>(sl, u);
#pragma unroll
    for (int c = 0; c < 8; ++c){
        int yy = (c << 4) + u;
        float2 v = sl[yy];
        base[(size_t)yy*256 + xl] = make_float2(v.x * (1.f/256.f), v.y * (1.f/256.f));
    }
}

// Inverse Z-pass: lines (b, y<128, x<128). Only z in [1,128) nonzero (mask),
// z>=128 zero. Write Re(z<128) * 1/256 directly to output.
__global__ void k_inv_z(float* __restrict__ out){
    __shared__ float2 s[16*257];
    int x0 = blockIdx.x << 4, y = blockIdx.y, b = blockIdx.z;
    int tid = threadIdx.x, xl = tid & 15, u = tid >> 4;
    const float2* base = g_B + ((size_t)b << 24) + ((size_t)y << 8) + x0;
    float2* sl = s + xl*257;
#pragma unroll
    for (int c = 0; c < 8; ++c){
        int zz = (c << 4) + u;                  // 0..127
        float2 v = make_float2(0.f, 0.f);
        if (zz >= 1) v = base[(size_t)zz*65536 + xl];
        sl[brev8(zz)]       = v;
        sl[brev8(zz + 128)] = make_float2(0.f, 0.f);
    }
    fft256_16t<1>(sl, u);
#pragma unroll
    for (int c = 0; c < 8; ++c){
        int zz = (c << 4) + u;
        out[(((size_t)b*128 + zz)*128 + y)*128 + (size_t)(x0 + xl)] = sl[zz].x * (1.f/256.f);
    }
}

extern "C" void kernel_launch(void* const* d_in, const int* in_sizes, int n_in,
                              void* d_out, int out_size){
    (void)in_sizes; (void)n_in; (void)out_size;
    const float* in = (const float*)d_in[0];
    float* out = (float*)d_out;

    k_fwd_x   <<<dim3(128, 128, 2), 128>>>(in);
    k_fwd_y   <<<dim3(16,  128, 2), 256>>>();
    k_fwd_z   <<<dim3(16,  256, 2), 256>>>();
    k_resample<<<dim3(256, 127, 2), 256>>>();
    k_inv_x   <<<dim3(256, 127, 2), 128>>>();
    k_inv_y   <<<dim3(8,   127, 2), 256>>>();
    k_inv_z   <<<dim3(8,   128, 2), 256>>>(out);
}

// round 2
// speedup vs baseline: 1.2156x; 1.2156x over previous
#include <cuda_runtime.h>
#include <cstdint>

#define PI_F 3.14159265358979323846f
// Scratch: g_A forward spectrum (only x<=128 columns valid), g_B inverse pipeline.
static __device__ float2 g_A[33554432];
static __device__ float2 g_B[33554432];

__device__ __forceinline__ float2 cmul(float2 a, float2 b){
    return make_float2(a.x*b.x - a.y*b.y, a.x*b.y + a.y*b.x);
}
__device__ __forceinline__ int brev8(int i){ return (int)(__brev((unsigned)i) >> 24); }

// 256-pt radix-2 DIT FFT, data bit-reversed in shared, 128 active threads.
template<int SIGN>
__device__ __forceinline__ void fft256_128t(float2* s, int tid){
#pragma unroll
    for (int st = 0; st < 8; ++st){
        int half = 1 << st;
        int pos = tid & (half - 1);
        int i0 = ((tid >> st) << (st + 1)) + pos;
        float ang = (float)SIGN * PI_F * (float)pos / (float)half;
        float sn, cs; __sincosf(ang, &sn, &cs);
        __syncthreads();
        float2 a = s[i0];
        float2 b = cmul(make_float2(cs, sn), s[i0 + half]);
        s[i0]        = make_float2(a.x + b.x, a.y + b.y);
        s[i0 + half] = make_float2(a.x - b.x, a.y - b.y);
    }
    __syncthreads();
}

// Variant callable by 256 threads (upper 128 idle but join the syncs).
template<int SIGN>
__device__ __forceinline__ void fft256_256t(float2* s, int tid){
#pragma unroll
    for (int st = 0; st < 8; ++st){
        __syncthreads();
        if (tid < 128){
            int half = 1 << st;
            int pos = tid & (half - 1);
            int i0 = ((tid >> st) << (st + 1)) + pos;
            float ang = (float)SIGN * PI_F * (float)pos / (float)half;
            float sn, cs; __sincosf(ang, &sn, &cs);
            float2 a = s[i0];
            float2 b = cmul(make_float2(cs, sn), s[i0 + half]);
            s[i0]        = make_float2(a.x + b.x, a.y + b.y);
            s[i0 + half] = make_float2(a.x - b.x, a.y - b.y);
        }
    }
    __syncthreads();
}

// 16 threads per line (u in [0,16)), 8 butterflies each per stage.
template<int SIGN>
__device__ __forceinline__ void fft256_16t(float2* s, int u){
#pragma unroll
    for (int st = 0; st < 8; ++st){
        int half = 1 << st;
        __syncthreads();
#pragma unroll
        for (int k = 0; k < 8; ++k){
            int j = u + (k << 4);
            int pos = j & (half - 1);
            int i0 = ((j >> st) << (st + 1)) + pos;
            float ang = (float)SIGN * PI_F * (float)pos / (float)half;
            float sn, cs; __sincosf(ang, &sn, &cs);
            float2 a = s[i0];
            float2 b = cmul(make_float2(cs, sn), s[i0 + half]);
            s[i0]        = make_float2(a.x + b.x, a.y + b.y);
            s[i0 + half] = make_float2(a.x - b.x, a.y - b.y);
        }
    }
    __syncthreads();
}

// Forward X-pass fused with prep: v = sqrt(relu(in * (z/127)^2)), zero-pad to 256.
// Writes only x in [0,128] (Hermitian: x>128 reconstructed in resample).
__global__ void k_fwd_x(const float* __restrict__ in){
    __shared__ float2 s[256];
    int y = blockIdx.x, zz = blockIdx.y, b = blockIdx.z;
    int tid = threadIdx.x;
    float g = (float)zz * (1.0f/127.0f);
    float g2 = g*g;
    const float* row = in + (((size_t)b*128 + zz)*128 + y)*128;
#pragma unroll
    for (int h = 0; h < 2; ++h){
        int i = tid + (h << 7);
        int src = brev8(i);
        float v = 0.0f;
        if (src < 128) v = sqrtf(fmaxf(row[src]*g2, 0.0f));
        s[i] = make_float2(v, 0.0f);
    }
    fft256_128t<-1>(s, tid);
    float2* outl = g_A + (((size_t)b*256 + zz)*256 + y)*256;
    outl[tid] = s[tid];
    if (tid == 0) outl[128] = s[128];
}

// Forward Y-pass: only x columns [0,128]. Read y<128 (zero-pad), write all y.
__global__ void k_fwd_y(){
    __shared__ float2 s[16*257];
    int x0 = blockIdx.x << 4, zz = blockIdx.y, b = blockIdx.z;
    int tid = threadIdx.x, xl = tid & 15, u = tid >> 4;
    bool valid = (x0 + xl) <= 128;
    float2* base = g_A + ((size_t)b << 24) + ((size_t)zz << 16) + x0;
    float2* sl = s + xl*257;
#pragma unroll
    for (int c = 0; c < 8; ++c){
        int yy = (c << 4) + u;
        float2 v = make_float2(0.f, 0.f);
        if (valid) v = base[(size_t)yy*256 + xl];
        sl[brev8(yy)]       = v;
        sl[brev8(yy + 128)] = make_float2(0.f, 0.f);
    }
    fft256_16t<-1>(sl, u);
    if (valid){
#pragma unroll
        for (int c = 0; c < 16; ++c){
            int yy = (c << 4) + u;
            base[(size_t)yy*256 + xl] = sl[yy];
        }
    }
}

// Forward Z-pass: only x columns [0,128]. Read z<128 (zero-pad), write all z.
__global__ void k_fwd_z(){
    __shared__ float2 s[16*257];
    int x0 = blockIdx.x << 4, y = blockIdx.y, b = blockIdx.z;
    int tid = threadIdx.x, xl = tid & 15, u = tid >> 4;
    bool valid = (x0 + xl) <= 128;
    float2* base = g_A + ((size_t)b << 24) + ((size_t)y << 8) + x0;
    float2* sl = s + xl*257;
#pragma unroll
    for (int c = 0; c < 8; ++c){
        int zz = (c << 4) + u;
        float2 v = make_float2(0.f, 0.f);
        if (valid) v = base[(size_t)zz*65536 + xl];
        sl[brev8(zz)]       = v;
        sl[brev8(zz + 128)] = make_float2(0.f, 0.f);
    }
    fft256_16t<-1>(sl, u);
    if (valid){
#pragma unroll
        for (int c = 0; c < 16; ++c){
            int zz = (c << 4) + u;
            base[(size_t)zz*65536 + xl] = sl[zz];
        }
    }
}

// Fused Stolt resample + inverse X FFT.
// One block = one (b, jz, jy) output line, thread jx in [0,256).
// Sample value computed in registers (Hermitian conj reconstruction for
// x>128), scattered bit-reversed into shared, 256-pt inverse FFT, write
// only x<128 (truncated by final crop) scaled by 1/256.
__global__ void k_resample_invx(){
    __shared__ float2 s[256];
    int jx = threadIdx.x;
    int jy = blockIdx.x;
    int jz = blockIdx.y + 1;        // 1..127 (z mask kills the rest)
    int b  = blockIdx.z;
    int sx = jx ^ 128, sy = jy ^ 128;
    float gz = (float)jz * (1.0f/128.0f);                 // sz-128 = jz
    float gy = (float)(sy - 128) * (1.0f/128.0f);
    float gx = (float)(sx - 128) * (1.0f/128.0f);
    const float fk = 0.1024f;       // (N*trange/(M*width*4))^2
    float gznew = sqrtf(fk*(gx*gx + gy*gy) + gz*gz);
    float pz = ((gznew + 1.0f)*256.0f - 1.0f)*0.5f;       // >= 128.5
    float z0f = floorf(pz);
    float dz = pz - z0f;
    int z0 = (int)z0f;
    float accx = 0.f, accy = 0.f;
    const float2* Ab = g_A + ((size_t)b << 24);
#pragma unroll
    for (int tz = 0; tz < 2; ++tz){
        int iz = z0 + tz;
        if (iz > 255) continue;     // iz >= 128 always
        int izu = iz ^ 128;                     // in [0,127]
        int izn = (256 - izu) & 255;
        float sxa = 0.f, sya = 0.f;
#pragma unroll
        for (int ty = 0; ty < 2; ++ty){
            int iy = sy - 1 + ty;
            if (iy < 0) continue;
            int iyu = iy ^ 128;
            int iyn = (256 - iyu) & 255;
#pragma unroll
            for (int tx = 0; tx < 2; ++tx){
                int ix = sx - 1 + tx;
                if (ix < 0) continue;
                int ixu = ix ^ 128;
                float2 v;
                if (ixu <= 128){
                    v = __ldg(&Ab[((size_t)izu << 16) + ((size_t)iyu << 8) + (size_t)ixu]);
                    sxa += v.x; sya += v.y;
                } else {
                    v = __ldg(&Ab[((size_t)izn << 16) + ((size_t)iyn << 8) + (size_t)(256 - ixu)]);
                    sxa += v.x; sya -= v.y;     // conjugate
                }
            }
        }
        float wz = tz ? dz : (1.0f - dz);
        accx += wz * sxa; accy += wz * sya;
    }
    float fac = 0.25f * gz / (gznew + 1e-8f);
    s[brev8(jx)] = make_float2(accx * fac, accy * fac);
    fft256_256t<1>(s, jx);
    if (jx < 128){
        float2 v = s[jx];
        g_B[((size_t)b << 24) + ((size_t)jz << 16) + ((size_t)jy << 8) + (size_t)jx]
            = make_float2(v.x * (1.f/256.f), v.y * (1.f/256.f));
    }
}

// Inverse Y-pass: lines (b, z in [1,128), x<128). Read all y, write y<128 (scaled).
__global__ void k_inv_y(){
    __shared__ float2 s[16*257];
    int x0 = blockIdx.x << 4, zz = blockIdx.y + 1, b = blockIdx.z;
    int tid = threadIdx.x, xl = tid & 15, u = tid >> 4;
    float2* base = g_B + ((size_t)b << 24) + ((size_t)zz << 16) + x0;
    float2* sl = s + xl*257;
#pragma unroll
    for (int c = 0; c < 16; ++c){
        int yy = (c << 4) + u;
        sl[brev8(yy)] = base[(size_t)yy*256 + xl];
    }
    fft256_16t<1>(sl, u);
#pragma unroll
    for (int c = 0; c < 8; ++c){
        int yy = (c << 4) + u;
        float2 v = sl[yy];
        base[(size_t)yy*256 + xl] = make_float2(v.x * (1.f/256.f), v.y * (1.f/256.f));
    }
}

// Inverse Z-pass: lines (b, y<128, x<128). Only z in [1,128) nonzero (mask).
// Write Re(z<128) * 1/256 directly to output.
__global__ void k_inv_z(float* __restrict__ out){
    __shared__ float2 s[16*257];
    int x0 = blockIdx.x << 4, y = blockIdx.y, b = blockIdx.z;
    int tid = threadIdx.x, xl = tid & 15, u = tid >> 4;
    const float2* base = g_B + ((size_t)b << 24) + ((size_t)y << 8) + x0;
    float2* sl = s + xl*257;
#pragma unroll
    for (int c = 0; c < 8; ++c){
        int zz = (c << 4) + u;                  // 0..127
        float2 v = make_float2(0.f, 0.f);
        if (zz >= 1) v = base[(size_t)zz*65536 + xl];
        sl[brev8(zz)]       = v;
        sl[brev8(zz + 128)] = make_float2(0.f, 0.f);
    }
    fft256_16t<1>(sl, u);
#pragma unroll
    for (int c = 0; c < 8; ++c){
        int zz = (c << 4) + u;
        out[(((size_t)b*128 + zz)*128 + y)*128 + (size_t)(x0 + xl)] = sl[zz].x * (1.f/256.f);
    }
}

extern "C" void kernel_launch(void* const* d_in, const int* in_sizes, int n_in,
                              void* d_out, int out_size){
    (void)in_sizes; (void)n_in; (void)out_size;
    const float* in = (const float*)d_in[0];
    float* out = (float*)d_out;

    k_fwd_x        <<<dim3(128, 128, 2), 128>>>(in);
    k_fwd_y        <<<dim3(9,   128, 2), 256>>>();
    k_fwd_z        <<<dim3(9,   256, 2), 256>>>();
    k_resample_invx<<<dim3(256, 127, 2), 256>>>();
    k_inv_y        <<<dim3(8,   127, 2), 256>>>();
    k_inv_z        <<<dim3(8,   128, 2), 256>>>(out);
}

// round 3
// speedup vs baseline: 1.7240x; 1.4182x over previous
#include <cuda_runtime.h>
#include <cstdint>

#define PI_F 3.14159265358979323846f
static __device__ float2 g_A[33554432];
static __device__ float2 g_B[33554432];

__device__ __forceinline__ float2 cmul(float2 a, float2 b){
    return make_float2(a.x*b.x - a.y*b.y, a.x*b.y + a.y*b.x);
}
// base-4 digit reversal of an 8-bit index
__device__ __forceinline__ int drev4(int i){
    return ((i & 3) << 6) | (((i >> 2) & 3) << 4) | (((i >> 4) & 3) << 2) | ((i >> 6) & 3);
}

// 256-pt radix-4 DIT FFT in shared memory. Input stored in drev4 order.
// NT threads per line, each does 64/NT butterflies per stage. 4 stages.
// __syncthreads() is block-wide: all lines in a block run in lockstep.
template<int SIGN, int NT>
__device__ __forceinline__ void fft256_r4(float2* s, int t){
#pragma unroll
    for (int st = 0; st < 4; ++st){
        int L = 1 << (2*st);
        __syncthreads();
#pragma unroll
        for (int k = 0; k < 64/NT; ++k){
            int j = t + k*NT;
            int p = j & (L - 1);
            int base = ((j >> (2*st)) << (2*st + 2)) + p;
            float ang = (float)SIGN * (2.0f*PI_F) * (float)p / (float)(4*L);
            float sn, cs; __sincosf(ang, &sn, &cs);
            float2 w1 = make_float2(cs, sn);
            float2 w2 = make_float2(cs*cs - sn*sn, 2.0f*cs*sn);
            float2 w3 = cmul(w1, w2);
            float2 a0 = s[base];
            float2 a1 = cmul(w1, s[base + L]);
            float2 a2 = cmul(w2, s[base + 2*L]);
            float2 a3 = cmul(w3, s[base + 3*L]);
            float2 t02p = make_float2(a0.x + a2.x, a0.y + a2.y);
            float2 t02m = make_float2(a0.x - a2.x, a0.y - a2.y);
            float2 t13p = make_float2(a1.x + a3.x, a1.y + a3.y);
            float2 t13m = make_float2(a1.x - a3.x, a1.y - a3.y);
            // jt = (SIGN*i) * t13m
            float2 jt = (SIGN < 0) ? make_float2(t13m.y, -t13m.x)
                                   : make_float2(-t13m.y, t13m.x);
            s[base]         = make_float2(t02p.x + t13p.x, t02p.y + t13p.y);
            s[base + L]     = make_float2(t02m.x + jt.x,   t02m.y + jt.y);
            s[base + 2*L]   = make_float2(t02p.x - t13p.x, t02p.y - t13p.y);
            s[base + 3*L]   = make_float2(t02m.x - jt.x,   t02m.y - jt.y);
        }
    }
    __syncthreads();
}

// Forward X + prep: v = sqrt(relu(in*(z/127)^2)), pad to 256, store x<=128 only.
// Block: 2 lines x 64 threads.
__global__ void k_fwd_x(const float* __restrict__ in){
    __shared__ float2 s[2*256];
    int tid = threadIdx.x;
    int l = tid >> 6, t = tid & 63;
    int y = (blockIdx.x << 1) + l;
    int zz = blockIdx.y, b = blockIdx.z;
    float g = (float)zz * (1.0f/127.0f);
    float g2 = g*g;
    const float* row = in + (((size_t)b*128 + zz)*128 + y)*128;
    float2* sl = s + (l << 8);
#pragma unroll
    for (int k = 0; k < 4; ++k){
        int j = t + (k << 6);
        int src = drev4(j);
        float v = 0.0f;
        if (src < 128) v = sqrtf(fmaxf(row[src]*g2, 0.0f));
        sl[j] = make_float2(v, 0.0f);
    }
    fft256_r4<-1,64>(sl, t);
    float2* outl = g_A + (((size_t)b*256 + zz)*256 + y)*256;
    outl[t]      = sl[t];
    outl[t + 64] = sl[t + 64];
    if (t == 0) outl[128] = sl[128];
}

// Forward Y: x columns [0,128]. Read y<128 (zero-pad), write all 256 y.
// Block: 16 x-lines x 16 threads.
__global__ void k_fwd_y(){
    __shared__ float2 s[16*257];
    int x0 = blockIdx.x << 4, zz = blockIdx.y, b = blockIdx.z;
    int tid = threadIdx.x, xl = tid & 15, u = tid >> 4;
    bool valid = (x0 + xl) <= 128;
    float2* base = g_A + ((size_t)b << 24) + ((size_t)zz << 16) + x0;
    float2* sl = s + xl*257;
#pragma unroll
    for (int c = 0; c < 8; ++c){
        int yy = (c << 4) + u;
        float2 v = make_float2(0.f, 0.f);
        if (valid) v = base[(size_t)yy*256 + xl];
        sl[drev4(yy)]       = v;
        sl[drev4(yy + 128)] = make_float2(0.f, 0.f);
    }
    fft256_r4<-1,16>(sl, u);
    if (valid){
#pragma unroll
        for (int c = 0; c < 16; ++c){
            int yy = (c << 4) + u;
            base[(size_t)yy*256 + xl] = sl[yy];
        }
    }
}

// Forward Z: x columns [0,128]. Read z<128 (zero-pad), write all 256 z.
__global__ void k_fwd_z(){
    __shared__ float2 s[16*257];
    int x0 = blockIdx.x << 4, y = blockIdx.y, b = blockIdx.z;
    int tid = threadIdx.x, xl = tid & 15, u = tid >> 4;
    bool valid = (x0 + xl) <= 128;
    float2* base = g_A + ((size_t)b << 24) + ((size_t)y << 8) + x0;
    float2* sl = s + xl*257;
#pragma unroll
    for (int c = 0; c < 8; ++c){
        int zz = (c << 4) + u;
        float2 v = make_float2(0.f, 0.f);
        if (valid) v = base[(size_t)zz*65536 + xl];
        sl[drev4(zz)]       = v;
        sl[drev4(zz + 128)] = make_float2(0.f, 0.f);
    }
    fft256_r4<-1,16>(sl, u);
    if (valid){
#pragma unroll
        for (int c = 0; c < 16; ++c){
            int zz = (c << 4) + u;
            base[(size_t)zz*65536 + xl] = sl[zz];
        }
    }
}

// Fused Stolt resample + inverse X FFT.
// Block: 4 jy-lines x 64 threads; each thread computes 4 samples.
// Hermitian conj reconstruction for x>128. 1/256 folded into fac.
__global__ void k_resample_invx(){
    __shared__ float2 s[4*256];
    int tid = threadIdx.x;
    int line = tid >> 6, t = tid & 63;
    int jy = (blockIdx.x << 2) + line;
    int jz = blockIdx.y + 1;        // 1..127
    int b  = blockIdx.z;
    int sy = jy ^ 128;
    float gz = (float)jz * (1.0f/128.0f);
    float gy = (float)(sy - 128) * (1.0f/128.0f);
    const float fk = 0.1024f;
    float gyz = fk*gy*gy + gz*gz;
    const float2* Ab = g_A + ((size_t)b << 24);
    float2* sl = s + (line << 8);
    // y neighbors are jx-independent: hoist.
    int iyA = sy - 1, iyB = sy;
    bool vyA = (iyA >= 0);
    int iyuA = iyA ^ 128, iynA = (256 - iyuA) & 255;
    int iyuB = iyB ^ 128, iynB = (256 - iyuB) & 255;
#pragma unroll
    for (int k = 0; k < 4; ++k){
        int jx = t + (k << 6);
        int sx = jx ^ 128;
        float gx = (float)(sx - 128) * (1.0f/128.0f);
        float gznew = sqrtf(fk*gx*gx + gyz);
        float pz = (gznew + 1.0f)*128.0f - 0.5f;    // >= 128.5
        float z0f = floorf(pz);
        float dz = pz - z0f;
        int z0 = (int)z0f;
        float accx = 0.f, accy = 0.f;
#pragma unroll
        for (int tz = 0; tz < 2; ++tz){
            int iz = z0 + tz;
            if (iz > 255) continue;                 // iz >= 128 always
            int izu = iz ^ 128;
            int izn = (256 - izu) & 255;
            float sxa = 0.f, sya = 0.f;
#pragma unroll
            for (int ty = 0; ty < 2; ++ty){
                if (ty == 0 && !vyA) continue;
                int iyu = ty ? iyuB : iyuA;
                int iyn = ty ? iynB : iynA;
#pragma unroll
                for (int tx = 0; tx < 2; ++tx){
                    int ix = sx - 1 + tx;
                    if (ix < 0) continue;
                    int ixu = ix ^ 128;
                    float2 v;
                    if (ixu <= 128){
                        v = __ldg(&Ab[((size_t)izu << 16) + ((size_t)iyu << 8) + (size_t)ixu]);
                        sxa += v.x; sya += v.y;
                    } else {
                        v = __ldg(&Ab[((size_t)izn << 16) + ((size_t)iyn << 8) + (size_t)(256 - ixu)]);
                        sxa += v.x; sya -= v.y;     // conjugate
                    }
                }
            }
            float wz = tz ? dz : (1.0f - dz);
            accx += wz * sxa; accy += wz * sya;
        }
        float fac = gz / (gznew + 1e-8f) * (0.25f/256.0f);
        sl[drev4(jx)] = make_float2(accx * fac, accy * fac);
    }
    fft256_r4<1,64>(sl, t);
    size_t o = ((size_t)b << 24) + ((size_t)jz << 16) + ((size_t)jy << 8);
    g_B[o + t]      = sl[t];
    g_B[o + t + 64] = sl[t + 64];
}

// Inverse Y: lines (b, z in [1,128), x<128). Read all y, write y<128 (scaled).
__global__ void k_inv_y(){
    __shared__ float2 s[16*257];
    int x0 = blockIdx.x << 4, zz = blockIdx.y + 1, b = blockIdx.z;
    int tid = threadIdx.x, xl = tid & 15, u = tid >> 4;
    float2* base = g_B + ((size_t)b << 24) + ((size_t)zz << 16) + x0;
    float2* sl = s + xl*257;
#pragma unroll
    for (int c = 0; c < 16; ++c){
        int yy = (c << 4) + u;
        sl[drev4(yy)] = base[(size_t)yy*256 + xl];
    }
    fft256_r4<1,16>(sl, u);
#pragma unroll
    for (int c = 0; c < 8; ++c){
        int yy = (c << 4) + u;
        float2 v = sl[yy];
        base[(size_t)yy*256 + xl] = make_float2(v.x * (1.f/256.f), v.y * (1.f/256.f));
    }
}

// Inverse Z: lines (b, y<128, x<128). Only z in [1,128) nonzero.
// Write Re(z<128) * 1/256 straight to output.
__global__ void k_inv_z(float* __restrict__ out){
    __shared__ float2 s[16*257];
    int x0 = blockIdx.x << 4, y = blockIdx.y, b = blockIdx.z;
    int tid = threadIdx.x, xl = tid & 15, u = tid >> 4;
    const float2* base = g_B + ((size_t)b << 24) + ((size_t)y << 8) + x0;
    float2* sl = s + xl*257;
#pragma unroll
    for (int c = 0; c < 8; ++c){
        int zz = (c << 4) + u;                  // 0..127
        float2 v = make_float2(0.f, 0.f);
        if (zz >= 1) v = base[(size_t)zz*65536 + xl];
        sl[drev4(zz)]       = v;
        sl[drev4(zz + 128)] = make_float2(0.f, 0.f);
    }
    fft256_r4<1,16>(sl, u);
#pragma unroll
    for (int c = 0; c < 8; ++c){
        int zz = (c << 4) + u;
        out[(((size_t)b*128 + zz)*128 + y)*128 + (size_t)(x0 + xl)] = sl[zz].x * (1.f/256.f);
    }
}

extern "C" void kernel_launch(void* const* d_in, const int* in_sizes, int n_in,
                              void* d_out, int out_size){
    (void)in_sizes; (void)n_in; (void)out_size;
    const float* in = (const float*)d_in[0];
    float* out = (float*)d_out;

    k_fwd_x        <<<dim3(64,  128, 2), 128>>>(in);
    k_fwd_y        <<<dim3(9,   128, 2), 256>>>();
    k_fwd_z        <<<dim3(9,   256, 2), 256>>>();
    k_resample_invx<<<dim3(64,  127, 2), 256>>>();
    k_inv_y        <<<dim3(8,   127, 2), 256>>>();
    k_inv_z        <<<dim3(8,   128, 2), 256>>>(out);
}